// round 4
// baseline (speedup 1.0000x reference)
#include <cuda_runtime.h>
#include <cuda_fp16.h>

// Problem constants
#define B_   2
#define T_   8
#define BT_  16
#define NQ_  128
#define NK_  128
#define DIN_ 64
#define DOUT_ 256
#define DP_  128     // d-pairs (DOUT_/2), half2-packed along d
#define DPC_ 64      // d-pairs per staged chunk
#define KPITCH_ 68   // words per K row in smem (68 % 32 == 4 -> conflict-free LDS.128)

// Projected Q/K in half2 (packed d-pairs). Device globals = legal scratch.
__device__ __half2 g_Qh[B_ * NQ_ * DP_];     // 256 rows x 128 half2
__device__ __half2 g_Kh[BT_ * NK_ * DP_];    // 2048 rows x 128 half2

__device__ __forceinline__ unsigned h2tanh_u(unsigned x) {
    unsigned r;
    asm("tanh.approx.f16x2 %0, %1;" : "=r"(r) : "r"(x));
    return r;
}
__device__ __forceinline__ unsigned hadd2_u(unsigned a, unsigned b) {
    __half2 r = __hadd2(*reinterpret_cast<__half2*>(&a),
                        *reinterpret_cast<__half2*>(&b));
    return *reinterpret_cast<unsigned*>(&r);
}

// ---------------------------------------------------------------------------
// Kernel 1: projections (fp32 math, half2 output).
// ---------------------------------------------------------------------------
__global__ void __launch_bounds__(256) proj_kernel(
    const float* __restrict__ query, const float* __restrict__ keys,
    const float* __restrict__ Wq,    const float* __restrict__ Wk,
    const float* __restrict__ bk)
{
    __shared__ float in_sh[16][DIN_];

    const int blk = blockIdx.x;            // 0..143 (16 Q blocks, 128 K blocks)
    const bool isQ = (blk < 16);
    const int r0 = (isQ ? blk : (blk - 16)) * 16;
    const float* __restrict__ in = isQ ? query : keys;
    const float* __restrict__ W  = isQ ? Wq    : Wk;
    __half2* __restrict__ outb   = isQ ? g_Qh  : g_Kh;

    const int tid = threadIdx.x;
    const int cg = tid & 63;
    const int rg = tid >> 6;

    {
        const int r = tid >> 4, s = tid & 15;
        *(float4*)&in_sh[r][s * 4] =
            *(const float4*)(in + (size_t)(r0 + r) * DIN_ + s * 4);
    }
    __syncthreads();

    float4 bias = make_float4(0.f, 0.f, 0.f, 0.f);
    if (!isQ) bias = *(const float4*)(bk + cg * 4);

    float4 acc[4];
#pragma unroll
    for (int rr = 0; rr < 4; rr++) acc[rr] = bias;

#pragma unroll
    for (int ic = 0; ic < 8; ic++) {
        float4 wv[8];
#pragma unroll
        for (int i = 0; i < 8; i++)
            wv[i] = *(const float4*)(W + (size_t)(ic * 8 + i) * DOUT_ + cg * 4);
#pragma unroll
        for (int rr = 0; rr < 4; rr++) {
            const int row = rg * 4 + rr;
#pragma unroll
            for (int i4 = 0; i4 < 2; i4++) {
                float4 xv = *(const float4*)&in_sh[row][ic * 8 + i4 * 4];
#pragma unroll
                for (int q = 0; q < 4; q++) {
                    const float x = (q == 0) ? xv.x : (q == 1) ? xv.y
                                  : (q == 2) ? xv.z : xv.w;
                    const float4 w4 = wv[i4 * 4 + q];
                    acc[rr].x = fmaf(x, w4.x, acc[rr].x);
                    acc[rr].y = fmaf(x, w4.y, acc[rr].y);
                    acc[rr].z = fmaf(x, w4.z, acc[rr].z);
                    acc[rr].w = fmaf(x, w4.w, acc[rr].w);
                }
            }
        }
    }

#pragma unroll
    for (int rr = 0; rr < 4; rr++) {
        __half2 p0 = __floats2half2_rn(acc[rr].x, acc[rr].y);
        __half2 p1 = __floats2half2_rn(acc[rr].z, acc[rr].w);
        __half2* dst = outb + (size_t)(r0 + rg * 4 + rr) * DP_ + cg * 2;
        dst[0] = p0;
        dst[1] = p1;
    }
}

// ---------------------------------------------------------------------------
// Kernel 2: scores + fused softmax.
// Grid 256 x 256 thr (8 warps). Warp w -> query row q0+w.
// Lane l -> nk {l, l+32, l+64, l+96}. K staged in 2 chunks of 64 dp,
// pitch-68 words -> conflict-free LDS.128. Per 8-dp group: 8 front-loaded
// LDS.128 (K), then 96 dependency-free HADD2/MUFU.TANH/HFMA2 ops.
// fp32 flush every 8 dp (identical numerics to R3).
// ---------------------------------------------------------------------------
__global__ void __launch_bounds__(256, 2) attn_kernel(
    const float* __restrict__ v, float* __restrict__ out)
{
    __shared__ unsigned k_sh[NK_ * KPITCH_];      // 34.8 KB
    __shared__ unsigned q_sh[8][DPC_];            // 2 KB
    __shared__ unsigned v_sh[DPC_];               // 256 B

    const int bt = blockIdx.x >> 4;
    const int q0 = (blockIdx.x & 15) << 3;
    const int b  = bt >> 3;

    const int tid  = threadIdx.x;
    const int w    = tid >> 5;
    const int lane = tid & 31;

    const __half2* __restrict__ kbase = g_Kh + (size_t)(bt * NK_) * DP_;
    const __half2* __restrict__ qbase = g_Qh + (size_t)(b * NQ_ + q0) * DP_;

    float acc0 = 0.f, acc1 = 0.f, acc2 = 0.f, acc3 = 0.f;

#pragma unroll 1
    for (int c = 0; c < DP_ / DPC_; c++) {
        const int d0 = c * DPC_;

        // Stage K chunk: 128 rows x 16 uint4 (8 per thread), pitch 68 words
#pragma unroll
        for (int e = tid; e < NK_ * 16; e += 256) {
            const int nk = e >> 4, s = e & 15;
            uint4 t = *(const uint4*)(kbase + (size_t)nk * DP_ + d0 + s * 4);
            *(uint4*)&k_sh[nk * KPITCH_ + s * 4] = t;
        }
        // Stage Q chunk: 8 rows x 16 uint4
        if (tid < 128) {
            const int r = tid >> 4, s = tid & 15;
            *(uint4*)&q_sh[r][s * 4] =
                *(const uint4*)(qbase + (size_t)r * DP_ + d0 + s * 4);
        }
        // Stage v chunk (fp32 -> half2)
        if (tid < DPC_) {
            float2 vv = *(const float2*)(v + 2 * (d0 + tid));
            __half2 h = __floats2half2_rn(vv.x, vv.y);
            v_sh[tid] = *reinterpret_cast<unsigned*>(&h);
        }
        __syncthreads();

        const unsigned* __restrict__ k0p = &k_sh[(lane      ) * KPITCH_];
        const unsigned* __restrict__ k1p = &k_sh[(lane + 32 ) * KPITCH_];
        const unsigned* __restrict__ k2p = &k_sh[(lane + 64 ) * KPITCH_];
        const unsigned* __restrict__ k3p = &k_sh[(lane + 96 ) * KPITCH_];

#pragma unroll 2
        for (int dp8 = 0; dp8 < DPC_; dp8 += 8) {
            // Front-load all shared data for this 8-dp group (LDS.128 x12)
            unsigned k0[8], k1[8], k2[8], k3[8], qr[8], vr[8];
            *(uint4*)&k0[0] = *(const uint4*)(k0p + dp8);
            *(uint4*)&k0[4] = *(const uint4*)(k0p + dp8 + 4);
            *(uint4*)&k1[0] = *(const uint4*)(k1p + dp8);
            *(uint4*)&k1[4] = *(const uint4*)(k1p + dp8 + 4);
            *(uint4*)&k2[0] = *(const uint4*)(k2p + dp8);
            *(uint4*)&k2[4] = *(const uint4*)(k2p + dp8 + 4);
            *(uint4*)&k3[0] = *(const uint4*)(k3p + dp8);
            *(uint4*)&k3[4] = *(const uint4*)(k3p + dp8 + 4);
            *(uint4*)&qr[0] = *(const uint4*)&q_sh[w][dp8];
            *(uint4*)&qr[4] = *(const uint4*)&q_sh[w][dp8 + 4];
            *(uint4*)&vr[0] = *(const uint4*)&v_sh[dp8];
            *(uint4*)&vr[4] = *(const uint4*)&v_sh[dp8 + 4];

            __half2 h0 = __float2half2_rn(0.f);
            __half2 h1 = h0, h2 = h0, h3 = h0;
#pragma unroll
            for (int j = 0; j < 8; j++) {
                const unsigned t0 = h2tanh_u(hadd2_u(qr[j], k0[j]));
                const unsigned t1 = h2tanh_u(hadd2_u(qr[j], k1[j]));
                const unsigned t2 = h2tanh_u(hadd2_u(qr[j], k2[j]));
                const unsigned t3 = h2tanh_u(hadd2_u(qr[j], k3[j]));
                const __half2 vp = *reinterpret_cast<const __half2*>(&vr[j]);
                h0 = __hfma2(vp, *reinterpret_cast<const __half2*>(&t0), h0);
                h1 = __hfma2(vp, *reinterpret_cast<const __half2*>(&t1), h1);
                h2 = __hfma2(vp, *reinterpret_cast<const __half2*>(&t2), h2);
                h3 = __hfma2(vp, *reinterpret_cast<const __half2*>(&t3), h3);
            }
            // Flush fp16 sub-accumulators to fp32 (8-dp chains)
            float2 f0 = __half22float2(h0);
            float2 f1 = __half22float2(h1);
            float2 f2 = __half22float2(h2);
            float2 f3 = __half22float2(h3);
            acc0 += f0.x + f0.y;
            acc1 += f1.x + f1.y;
            acc2 += f2.x + f2.y;
            acc3 += f3.x + f3.y;
        }
        __syncthreads();
    }

    // Fused softmax over nk (warp owns the full 128-wide row)
    float m = fmaxf(fmaxf(acc0, acc1), fmaxf(acc2, acc3));
#pragma unroll
    for (int o = 16; o > 0; o >>= 1)
        m = fmaxf(m, __shfl_xor_sync(0xffffffffu, m, o));

    const float e0 = __expf(acc0 - m);
    const float e1 = __expf(acc1 - m);
    const float e2 = __expf(acc2 - m);
    const float e3 = __expf(acc3 - m);
    float ssum = e0 + e1 + e2 + e3;
#pragma unroll
    for (int o = 16; o > 0; o >>= 1)
        ssum += __shfl_xor_sync(0xffffffffu, ssum, o);

    const float rinv = 1.0f / ssum;

    float* __restrict__ orow = out + (size_t)(bt * NQ_ + q0 + w) * NK_;
    orow[lane      ] = e0 * rinv;
    orow[lane + 32 ] = e1 * rinv;
    orow[lane + 64 ] = e2 * rinv;
    orow[lane + 96 ] = e3 * rinv;
}

// ---------------------------------------------------------------------------
extern "C" void kernel_launch(void* const* d_in, const int* in_sizes, int n_in,
                              void* d_out, int out_size)
{
    const float* query = (const float*)d_in[0];
    const float* keys  = (const float*)d_in[1];
    const float* Wq    = (const float*)d_in[2];
    const float* Wk    = (const float*)d_in[3];
    const float* bk    = (const float*)d_in[4];
    const float* v     = (const float*)d_in[5];
    float* out = (float*)d_out;

    proj_kernel<<<144, 256>>>(query, keys, Wq, Wk, bk);
    attn_kernel<<<256, 256>>>(v, out);
}

// round 5
// speedup vs baseline: 1.0077x; 1.0077x over previous
#include <cuda_runtime.h>
#include <cuda_fp16.h>

// Problem constants
#define B_   2
#define T_   8
#define BT_  16
#define NQ_  128
#define NK_  128
#define DIN_ 64
#define DOUT_ 256
#define DP_  128     // d-pairs (DOUT_/2), half2-packed along d
#define DPC_ 64      // d-pairs per staged chunk
#define KPITCH_ 68   // words per K row (68 % 32 == 4 -> conflict-free LDS.128)
#define NQC_ 4       // q rows per block

// Projected Q/K in half2 (packed d-pairs). Device globals = legal scratch.
__device__ __half2 g_Qh[B_ * NQ_ * DP_];     // 256 rows x 128 half2
__device__ __half2 g_Kh[BT_ * NK_ * DP_];    // 2048 rows x 128 half2

__device__ __forceinline__ unsigned h2tanh_u(unsigned x) {
    unsigned r;
    asm("tanh.approx.f16x2 %0, %1;" : "=r"(r) : "r"(x));
    return r;
}
__device__ __forceinline__ unsigned hadd2_u(unsigned a, unsigned b) {
    __half2 r = __hadd2(*reinterpret_cast<__half2*>(&a),
                        *reinterpret_cast<__half2*>(&b));
    return *reinterpret_cast<unsigned*>(&r);
}

// ---------------------------------------------------------------------------
// Kernel 1: projections (fp32 math, half2 output). Unchanged.
// ---------------------------------------------------------------------------
__global__ void __launch_bounds__(256) proj_kernel(
    const float* __restrict__ query, const float* __restrict__ keys,
    const float* __restrict__ Wq,    const float* __restrict__ Wk,
    const float* __restrict__ bk)
{
    __shared__ float in_sh[16][DIN_];

    const int blk = blockIdx.x;
    const bool isQ = (blk < 16);
    const int r0 = (isQ ? blk : (blk - 16)) * 16;
    const float* __restrict__ in = isQ ? query : keys;
    const float* __restrict__ W  = isQ ? Wq    : Wk;
    __half2* __restrict__ outb   = isQ ? g_Qh  : g_Kh;

    const int tid = threadIdx.x;
    const int cg = tid & 63;
    const int rg = tid >> 6;

    {
        const int r = tid >> 4, s = tid & 15;
        *(float4*)&in_sh[r][s * 4] =
            *(const float4*)(in + (size_t)(r0 + r) * DIN_ + s * 4);
    }
    __syncthreads();

    float4 bias = make_float4(0.f, 0.f, 0.f, 0.f);
    if (!isQ) bias = *(const float4*)(bk + cg * 4);

    float4 acc[4];
#pragma unroll
    for (int rr = 0; rr < 4; rr++) acc[rr] = bias;

#pragma unroll
    for (int ic = 0; ic < 8; ic++) {
        float4 wv[8];
#pragma unroll
        for (int i = 0; i < 8; i++)
            wv[i] = *(const float4*)(W + (size_t)(ic * 8 + i) * DOUT_ + cg * 4);
#pragma unroll
        for (int rr = 0; rr < 4; rr++) {
            const int row = rg * 4 + rr;
#pragma unroll
            for (int i4 = 0; i4 < 2; i4++) {
                float4 xv = *(const float4*)&in_sh[row][ic * 8 + i4 * 4];
#pragma unroll
                for (int q = 0; q < 4; q++) {
                    const float x = (q == 0) ? xv.x : (q == 1) ? xv.y
                                  : (q == 2) ? xv.z : xv.w;
                    const float4 w4 = wv[i4 * 4 + q];
                    acc[rr].x = fmaf(x, w4.x, acc[rr].x);
                    acc[rr].y = fmaf(x, w4.y, acc[rr].y);
                    acc[rr].z = fmaf(x, w4.z, acc[rr].z);
                    acc[rr].w = fmaf(x, w4.w, acc[rr].w);
                }
            }
        }
    }

#pragma unroll
    for (int rr = 0; rr < 4; rr++) {
        __half2 p0 = __floats2half2_rn(acc[rr].x, acc[rr].y);
        __half2 p1 = __floats2half2_rn(acc[rr].z, acc[rr].w);
        __half2* dst = outb + (size_t)(r0 + rg * 4 + rr) * DP_ + cg * 2;
        dst[0] = p0;
        dst[1] = p1;
    }
}

// ---------------------------------------------------------------------------
// Kernel 2: scores + fused softmax.
// Grid = BT * (NQ/4) = 512 blocks x 256 thr (8 warps).
// Warp w -> q row q0 + (w>>1), nk half h=(w&1): lane owns nk {64h+l, 64h+l+32}.
// All 512 blocks resident in one wave at 4 blocks/SM -> 32 warps on critical
// SMs (2x R4) to cover MUFU latency. Softmax: warp-local over the 64-nk half,
// then 2-warp combine per q row via smem.
// ---------------------------------------------------------------------------
__global__ void __launch_bounds__(256, 4) attn_kernel(
    const float* __restrict__ v, float* __restrict__ out)
{
    __shared__ unsigned k_sh[NK_ * KPITCH_];      // 34.8 KB
    __shared__ unsigned q_sh[NQC_][DPC_];         // 1 KB
    __shared__ unsigned v_sh[DPC_];               // 256 B
    __shared__ float sm_m[NQC_][2];
    __shared__ float sm_s[NQC_][2];

    const int bt = blockIdx.x >> 5;               // 0..15
    const int q0 = (blockIdx.x & 31) << 2;        // q chunk of 4
    const int b  = bt >> 3;

    const int tid  = threadIdx.x;
    const int w    = tid >> 5;
    const int lane = tid & 31;
    const int ql   = w >> 1;                      // local q row 0..3
    const int h    = w & 1;                       // nk half
    const int nkA  = (h << 6) + lane;             // nk for accA
    // nkB = nkA + 32

    const __half2* __restrict__ kbase = g_Kh + (size_t)(bt * NK_) * DP_;
    const __half2* __restrict__ qbase = g_Qh + (size_t)(b * NQ_ + q0) * DP_;

    float accA = 0.f, accB = 0.f;

#pragma unroll 1
    for (int c = 0; c < DP_ / DPC_; c++) {
        const int d0 = c * DPC_;

        // Stage K chunk: 128 rows x 16 uint4 (8 per thread), pitch 68 words
#pragma unroll
        for (int e = tid; e < NK_ * 16; e += 256) {
            const int nk = e >> 4, s = e & 15;
            uint4 t = *(const uint4*)(kbase + (size_t)nk * DP_ + d0 + s * 4);
            *(uint4*)&k_sh[nk * KPITCH_ + s * 4] = t;
        }
        // Stage Q chunk: 4 rows x 16 uint4
        if (tid < 64) {
            const int r = tid >> 4, s = tid & 15;
            *(uint4*)&q_sh[r][s * 4] =
                *(const uint4*)(qbase + (size_t)r * DP_ + d0 + s * 4);
        }
        // Stage v chunk (fp32 -> half2)
        if (tid >= 64 && tid < 64 + DPC_) {
            const int i = tid - 64;
            float2 vv = *(const float2*)(v + 2 * (d0 + i));
            __half2 hh = __floats2half2_rn(vv.x, vv.y);
            v_sh[i] = *reinterpret_cast<unsigned*>(&hh);
        }
        __syncthreads();

        const unsigned* __restrict__ kAp = &k_sh[nkA * KPITCH_];
        const unsigned* __restrict__ kBp = &k_sh[(nkA + 32) * KPITCH_];

#pragma unroll 2
        for (int dp8 = 0; dp8 < DPC_; dp8 += 8) {
            unsigned kA[8], kB[8], qr[8], vr[8];
            *(uint4*)&kA[0] = *(const uint4*)(kAp + dp8);
            *(uint4*)&kA[4] = *(const uint4*)(kAp + dp8 + 4);
            *(uint4*)&kB[0] = *(const uint4*)(kBp + dp8);
            *(uint4*)&kB[4] = *(const uint4*)(kBp + dp8 + 4);
            *(uint4*)&qr[0] = *(const uint4*)&q_sh[ql][dp8];
            *(uint4*)&qr[4] = *(const uint4*)&q_sh[ql][dp8 + 4];
            *(uint4*)&vr[0] = *(const uint4*)&v_sh[dp8];
            *(uint4*)&vr[4] = *(const uint4*)&v_sh[dp8 + 4];

            __half2 hA = __float2half2_rn(0.f);
            __half2 hB = hA;
#pragma unroll
            for (int j = 0; j < 8; j++) {
                const unsigned tA = h2tanh_u(hadd2_u(qr[j], kA[j]));
                const unsigned tB = h2tanh_u(hadd2_u(qr[j], kB[j]));
                const __half2 vp = *reinterpret_cast<const __half2*>(&vr[j]);
                hA = __hfma2(vp, *reinterpret_cast<const __half2*>(&tA), hA);
                hB = __hfma2(vp, *reinterpret_cast<const __half2*>(&tB), hB);
            }
            float2 fA = __half22float2(hA);
            float2 fB = __half22float2(hB);
            accA += fA.x + fA.y;
            accB += fB.x + fB.y;
        }
        __syncthreads();
    }

    // ---- Softmax: warp-local over 64-nk half, then 2-warp combine per q ----
    float mloc = fmaxf(accA, accB);
#pragma unroll
    for (int o = 16; o > 0; o >>= 1)
        mloc = fmaxf(mloc, __shfl_xor_sync(0xffffffffu, mloc, o));
    if (lane == 0) sm_m[ql][h] = mloc;
    __syncthreads();
    const float m = fmaxf(sm_m[ql][0], sm_m[ql][1]);

    const float eA = __expf(accA - m);
    const float eB = __expf(accB - m);
    float ssum = eA + eB;
#pragma unroll
    for (int o = 16; o > 0; o >>= 1)
        ssum += __shfl_xor_sync(0xffffffffu, ssum, o);
    if (lane == 0) sm_s[ql][h] = ssum;
    __syncthreads();
    const float rinv = 1.0f / (sm_s[ql][0] + sm_s[ql][1]);

    float* __restrict__ orow = out + (size_t)(bt * NQ_ + q0 + ql) * NK_;
    orow[nkA     ] = eA * rinv;
    orow[nkA + 32] = eB * rinv;
}

// ---------------------------------------------------------------------------
extern "C" void kernel_launch(void* const* d_in, const int* in_sizes, int n_in,
                              void* d_out, int out_size)
{
    const float* query = (const float*)d_in[0];
    const float* keys  = (const float*)d_in[1];
    const float* Wq    = (const float*)d_in[2];
    const float* Wk    = (const float*)d_in[3];
    const float* bk    = (const float*)d_in[4];
    const float* v     = (const float*)d_in[5];
    float* out = (float*)d_out;

    proj_kernel<<<144, 256>>>(query, keys, Wq, Wk, bk);
    attn_kernel<<<BT_ * (NQ_ / NQC_), 256>>>(v, out);
}

// round 6
// speedup vs baseline: 1.0088x; 1.0011x over previous
#include <cuda_runtime.h>
#include <cuda_fp16.h>

// Problem constants
#define B_   2
#define T_   8
#define BT_  16
#define NQ_  128
#define NK_  128
#define DIN_ 64
#define DOUT_ 256
#define DP_  128     // d-pairs (DOUT_/2), half2-packed along d
#define DPH_ 64      // d-pairs per d-half (this kernel's whole range)
#define KPITCH_ 68   // words per K row (68 % 32 == 4 -> conflict-free LDS.128)

// Device-global scratch (allocation-free per harness rules)
__device__ __half2 g_Qh[B_ * NQ_ * DP_];       // 256 rows x 128 half2
__device__ __half2 g_Kh[BT_ * NK_ * DP_];      // 2048 rows x 128 half2
__device__ float   g_P[2 * BT_ * NQ_ * NK_];   // partial scores per d-half (2 MB)

__device__ __forceinline__ unsigned h2tanh_u(unsigned x) {
    unsigned r;
    asm("tanh.approx.f16x2 %0, %1;" : "=r"(r) : "r"(x));
    return r;
}
__device__ __forceinline__ unsigned hadd2_u(unsigned a, unsigned b) {
    __half2 r = __hadd2(*reinterpret_cast<__half2*>(&a),
                        *reinterpret_cast<__half2*>(&b));
    return *reinterpret_cast<unsigned*>(&r);
}

// ---------------------------------------------------------------------------
// Kernel 1: projections (fp32 math, half2 output). Unchanged.
// ---------------------------------------------------------------------------
__global__ void __launch_bounds__(256) proj_kernel(
    const float* __restrict__ query, const float* __restrict__ keys,
    const float* __restrict__ Wq,    const float* __restrict__ Wk,
    const float* __restrict__ bk)
{
    __shared__ float in_sh[16][DIN_];

    const int blk = blockIdx.x;
    const bool isQ = (blk < 16);
    const int r0 = (isQ ? blk : (blk - 16)) * 16;
    const float* __restrict__ in = isQ ? query : keys;
    const float* __restrict__ W  = isQ ? Wq    : Wk;
    __half2* __restrict__ outb   = isQ ? g_Qh  : g_Kh;

    const int tid = threadIdx.x;
    const int cg = tid & 63;
    const int rg = tid >> 6;

    {
        const int r = tid >> 4, s = tid & 15;
        *(float4*)&in_sh[r][s * 4] =
            *(const float4*)(in + (size_t)(r0 + r) * DIN_ + s * 4);
    }
    __syncthreads();

    float4 bias = make_float4(0.f, 0.f, 0.f, 0.f);
    if (!isQ) bias = *(const float4*)(bk + cg * 4);

    float4 acc[4];
#pragma unroll
    for (int rr = 0; rr < 4; rr++) acc[rr] = bias;

#pragma unroll
    for (int ic = 0; ic < 8; ic++) {
        float4 wv[8];
#pragma unroll
        for (int i = 0; i < 8; i++)
            wv[i] = *(const float4*)(W + (size_t)(ic * 8 + i) * DOUT_ + cg * 4);
#pragma unroll
        for (int rr = 0; rr < 4; rr++) {
            const int row = rg * 4 + rr;
#pragma unroll
            for (int i4 = 0; i4 < 2; i4++) {
                float4 xv = *(const float4*)&in_sh[row][ic * 8 + i4 * 4];
#pragma unroll
                for (int q = 0; q < 4; q++) {
                    const float x = (q == 0) ? xv.x : (q == 1) ? xv.y
                                  : (q == 2) ? xv.z : xv.w;
                    const float4 w4 = wv[i4 * 4 + q];
                    acc[rr].x = fmaf(x, w4.x, acc[rr].x);
                    acc[rr].y = fmaf(x, w4.y, acc[rr].y);
                    acc[rr].z = fmaf(x, w4.z, acc[rr].z);
                    acc[rr].w = fmaf(x, w4.w, acc[rr].w);
                }
            }
        }
    }

#pragma unroll
    for (int rr = 0; rr < 4; rr++) {
        __half2 p0 = __floats2half2_rn(acc[rr].x, acc[rr].y);
        __half2 p1 = __floats2half2_rn(acc[rr].z, acc[rr].w);
        __half2* dst = outb + (size_t)(r0 + rg * 4 + rr) * DP_ + cg * 2;
        dst[0] = p0;
        dst[1] = p1;
    }
}

// ---------------------------------------------------------------------------
// Kernel 2: partial scores over a d-half.
// Grid = 16 bt x 16 qc x 2 dh = 512 blocks x 256 thr (one wave, 4 blocks/SM
// -> 32 warps/SM). Warp w -> q row qc*8+w; lane owns nk {l,l+32,l+64,l+96}
// = 4 independent tanh streams (128 chains/SM total). 4-dp front-loaded
// batches keep regs <= 64. Writes fp32 partial sums to g_P[dh].
// ---------------------------------------------------------------------------
__global__ void __launch_bounds__(256, 4) attn_partial_kernel(
    const float* __restrict__ v)
{
    __shared__ unsigned k_sh[NK_ * KPITCH_];      // 34.8 KB
    __shared__ unsigned q_sh[8][DPH_];            // 2 KB
    __shared__ unsigned v_sh[DPH_];               // 256 B

    const int blk = blockIdx.x;
    const int dh  = blk & 1;                      // d-half
    const int qc  = (blk >> 1) & 15;              // q chunk of 8
    const int bt  = blk >> 5;                     // 0..15
    const int b   = bt >> 3;
    const int d0  = dh * DPH_;                    // dp offset

    const int tid  = threadIdx.x;
    const int w    = tid >> 5;
    const int lane = tid & 31;

    const __half2* __restrict__ kbase = g_Kh + (size_t)(bt * NK_) * DP_ + d0;
    const __half2* __restrict__ qbase = g_Qh + (size_t)(b * NQ_ + qc * 8) * DP_ + d0;

    // Stage K: 128 rows x 16 uint4 (8 per thread), pitch 68 words
#pragma unroll
    for (int e = tid; e < NK_ * 16; e += 256) {
        const int nk = e >> 4, s = e & 15;
        uint4 t = *(const uint4*)(kbase + (size_t)nk * DP_ + s * 4);
        *(uint4*)&k_sh[nk * KPITCH_ + s * 4] = t;
    }
    // Stage Q: 8 rows x 16 uint4
    if (tid < 128) {
        const int r = tid >> 4, s = tid & 15;
        *(uint4*)&q_sh[r][s * 4] =
            *(const uint4*)(qbase + (size_t)r * DP_ + s * 4);
    }
    // Stage v (fp32 -> half2)
    if (tid >= 128 && tid < 128 + DPH_) {
        const int i = tid - 128;
        float2 vv = *(const float2*)(v + 2 * (d0 + i));
        __half2 hh = __floats2half2_rn(vv.x, vv.y);
        v_sh[i] = *reinterpret_cast<unsigned*>(&hh);
    }
    __syncthreads();

    const unsigned* __restrict__ kAp = &k_sh[(lane      ) * KPITCH_];
    const unsigned* __restrict__ kBp = &k_sh[(lane + 32 ) * KPITCH_];
    const unsigned* __restrict__ kCp = &k_sh[(lane + 64 ) * KPITCH_];
    const unsigned* __restrict__ kDp = &k_sh[(lane + 96 ) * KPITCH_];

    float accA = 0.f, accB = 0.f, accC = 0.f, accD = 0.f;

#pragma unroll 4
    for (int dp4 = 0; dp4 < DPH_; dp4 += 4) {
        // Front-load this 4-dp group: 6 x LDS.128
        unsigned kA[4], kB[4], kC[4], kD[4], qr[4], vr[4];
        *(uint4*)&kA[0] = *(const uint4*)(kAp + dp4);
        *(uint4*)&kB[0] = *(const uint4*)(kBp + dp4);
        *(uint4*)&kC[0] = *(const uint4*)(kCp + dp4);
        *(uint4*)&kD[0] = *(const uint4*)(kDp + dp4);
        *(uint4*)&qr[0] = *(const uint4*)&q_sh[w][dp4];
        *(uint4*)&vr[0] = *(const uint4*)&v_sh[dp4];

        __half2 hA = __float2half2_rn(0.f);
        __half2 hB = hA, hC = hA, hD = hA;
#pragma unroll
        for (int j = 0; j < 4; j++) {
            const unsigned tA = h2tanh_u(hadd2_u(qr[j], kA[j]));
            const unsigned tB = h2tanh_u(hadd2_u(qr[j], kB[j]));
            const unsigned tC = h2tanh_u(hadd2_u(qr[j], kC[j]));
            const unsigned tD = h2tanh_u(hadd2_u(qr[j], kD[j]));
            const __half2 vp = *reinterpret_cast<const __half2*>(&vr[j]);
            hA = __hfma2(vp, *reinterpret_cast<const __half2*>(&tA), hA);
            hB = __hfma2(vp, *reinterpret_cast<const __half2*>(&tB), hB);
            hC = __hfma2(vp, *reinterpret_cast<const __half2*>(&tC), hC);
            hD = __hfma2(vp, *reinterpret_cast<const __half2*>(&tD), hD);
        }
        // Flush fp16 sub-accumulators to fp32 (4-dp chains)
        float2 fA = __half22float2(hA);
        float2 fB = __half22float2(hB);
        float2 fC = __half22float2(hC);
        float2 fD = __half22float2(hD);
        accA += fA.x + fA.y;
        accB += fB.x + fB.y;
        accC += fC.x + fC.y;
        accD += fD.x + fD.y;
    }

    // Write partials: g_P[dh][bt][q][nk], coalesced 32-lane groups
    float* __restrict__ prow =
        g_P + ((size_t)dh * BT_ * NQ_ + (size_t)(bt * NQ_ + qc * 8 + w)) * NK_;
    prow[lane      ] = accA;
    prow[lane + 32 ] = accB;
    prow[lane + 64 ] = accC;
    prow[lane + 96 ] = accD;
}

// ---------------------------------------------------------------------------
// Kernel 3: combine d-halves + softmax.
// Grid 256 x 256 thr; warp handles one (bt,q) row, lane -> 4 nk via float4.
// ---------------------------------------------------------------------------
__global__ void __launch_bounds__(256) combine_kernel(float* __restrict__ out)
{
    const int tid  = threadIdx.x;
    const int w    = tid >> 5;
    const int lane = tid & 31;
    const int r    = blockIdx.x * 8 + w;          // 0..2047 = bt*128 + q

    const float* __restrict__ p0 = g_P + (size_t)r * NK_;
    const float* __restrict__ p1 = g_P + (size_t)(BT_ * NQ_ + r) * NK_;

    float4 a = *(const float4*)(p0 + lane * 4);
    float4 c = *(const float4*)(p1 + lane * 4);
    float4 s = make_float4(a.x + c.x, a.y + c.y, a.z + c.z, a.w + c.w);

    float m = fmaxf(fmaxf(s.x, s.y), fmaxf(s.z, s.w));
#pragma unroll
    for (int o = 16; o > 0; o >>= 1)
        m = fmaxf(m, __shfl_xor_sync(0xffffffffu, m, o));

    float4 e = make_float4(__expf(s.x - m), __expf(s.y - m),
                           __expf(s.z - m), __expf(s.w - m));
    float ssum = e.x + e.y + e.z + e.w;
#pragma unroll
    for (int o = 16; o > 0; o >>= 1)
        ssum += __shfl_xor_sync(0xffffffffu, ssum, o);

    const float rinv = 1.0f / ssum;
    float4 res = make_float4(e.x * rinv, e.y * rinv, e.z * rinv, e.w * rinv);
    *(float4*)(out + (size_t)r * NK_ + lane * 4) = res;
}

// ---------------------------------------------------------------------------
extern "C" void kernel_launch(void* const* d_in, const int* in_sizes, int n_in,
                              void* d_out, int out_size)
{
    const float* query = (const float*)d_in[0];
    const float* keys  = (const float*)d_in[1];
    const float* Wq    = (const float*)d_in[2];
    const float* Wk    = (const float*)d_in[3];
    const float* bk    = (const float*)d_in[4];
    const float* v     = (const float*)d_in[5];
    float* out = (float*)d_out;

    proj_kernel<<<144, 256>>>(query, keys, Wq, Wk, bk);
    attn_partial_kernel<<<512, 256>>>(v);
    combine_kernel<<<256, 256>>>(out);
}